// round 16
// baseline (speedup 1.0000x reference)
#include <cuda_runtime.h>
#include <cuda_fp16.h>
#include <cstdint>

#define NB 512   // batch
#define DD 512   // embed dim
#define OD 512   // out dim

// -------- scratch (no cudaMalloc allowed) --------
__device__ float g_h[NB * DD];
__device__ float g_logits[NB * DD];
__device__ float g_textw[NB * DD];
__device__ float g_outx[NB * DD];
__device__ float g_gate[NB * DD];
__device__ float g_tmp[NB * DD];
__device__ __half g_outxh[NB * DD];  // fp16 copy of outx
__device__ __half g_WoT[OD * DD];    // WoT[o][d] = fp16(Wo[d][o])

// ============================================================
// Helpers (plain sm_80+ PTX: mma.sync / ldmatrix / cp.async)
// ============================================================
__device__ __forceinline__ uint32_t smem_u32(const void* p) {
    uint32_t a;
    asm("{ .reg .u64 t; cvta.to.shared.u64 t, %1; cvt.u32.u64 %0, t; }"
        : "=r"(a) : "l"(p));
    return a;
}

#define CP_ASYNC_16(dst, src) \
    asm volatile("cp.async.cg.shared.global [%0], [%1], 16;" \
                 :: "r"((uint32_t)(dst)), "l"(src))
#define CP_ASYNC_COMMIT() asm volatile("cp.async.commit_group;" ::: "memory")
#define CP_ASYNC_WAIT0()  asm volatile("cp.async.wait_group 0;" ::: "memory")

__device__ __forceinline__ void ldsm_x4(uint32_t r[4], uint32_t addr) {
    asm volatile("ldmatrix.sync.aligned.m8n8.x4.shared.b16 {%0,%1,%2,%3}, [%4];"
                 : "=r"(r[0]), "=r"(r[1]), "=r"(r[2]), "=r"(r[3]) : "r"(addr));
}

__device__ __forceinline__ void mma_fp16(float c[4], const uint32_t a[4],
                                         const uint32_t b0, const uint32_t b1) {
    asm volatile(
        "mma.sync.aligned.m16n8k16.row.col.f32.f16.f16.f32 "
        "{%0,%1,%2,%3}, {%4,%5,%6,%7}, {%8,%9}, {%0,%1,%2,%3};"
        : "+f"(c[0]), "+f"(c[1]), "+f"(c[2]), "+f"(c[3])
        : "r"(a[0]), "r"(a[1]), "r"(a[2]), "r"(a[3]), "r"(b0), "r"(b1));
}

// ============================================================
// smem layout for big kernel (dynamic) — R10/R14 structure
// ============================================================
#define ASTRIDE 144
#define OFF_A0 0
#define OFF_A1 18432
#define OFF_B  36864
#define BUF_BYTES 55296
#define SMEM_BYTES (4096 + 2 * BUF_BYTES)   // 114688 -> 1 CTA/SM

// ============================================================
// Preamble small GEMM: BM=64, BN=32, BK=64, 128 threads,
// software-pipelined register-staged LDGs (8 iterations, 16 barriers).
// Per-thread k-order unchanged -> bit-identical accumulation.
// ============================================================
template <int ACT, bool WRITE_H>
__device__ __forceinline__ void gemm_small_body(
    const float* __restrict__ A, const float* __restrict__ W,
    const float* __restrict__ bias, float* __restrict__ C,
    __half* __restrict__ Ch, int m0, int n0)
{
    __shared__ float As[64][64];   // [k][m] 16KB
    __shared__ float Bs[64][36];   // [k][n] padded stride 36 (bank-safe)
    const int t = threadIdx.x;
    const int tx = t & 7, ty = t >> 3;
    const int am = t >> 1, akq = (t & 1) * 32;  // A: row am, 32 cols (8 float4)
    const int bk = t >> 1, bn = (t & 1) * 16;   // B: row bk, 16 cols (4 float4)

    float4 ra[8], rb[4];
    auto ldgTiles = [&](int k0) {
        #pragma unroll
        for (int q = 0; q < 8; q++)
            ra[q] = __ldg((const float4*)&A[(size_t)(m0 + am) * DD + k0 + akq + q * 4]);
        #pragma unroll
        for (int q = 0; q < 4; q++)
            rb[q] = __ldg((const float4*)&W[(size_t)(k0 + bk) * OD + n0 + bn + q * 4]);
    };

    float acc[4][4] = {};
    ldgTiles(0);

    for (int it = 0; it < 8; it++) {
        if (it) __syncthreads();               // consumers of prev tile done
        #pragma unroll
        for (int q = 0; q < 8; q++) {
            As[akq + q * 4 + 0][am] = ra[q].x;
            As[akq + q * 4 + 1][am] = ra[q].y;
            As[akq + q * 4 + 2][am] = ra[q].z;
            As[akq + q * 4 + 3][am] = ra[q].w;
        }
        #pragma unroll
        for (int q = 0; q < 4; q++)
            *(float4*)&Bs[bk][bn + q * 4] = rb[q];
        __syncthreads();                       // tile visible
        if (it < 7) ldgTiles((it + 1) * 64);   // prefetch hides behind FMA

        #pragma unroll
        for (int k = 0; k < 64; k++) {
            float a[4], b[4];
            *(float4*)a = *(const float4*)&As[k][ty * 4];
            *(float4*)b = *(const float4*)&Bs[k][tx * 4];
            #pragma unroll
            for (int r = 0; r < 4; r++)
                #pragma unroll
                for (int c = 0; c < 4; c++)
                    acc[r][c] += a[r] * b[c];
        }
    }

    #pragma unroll
    for (int r = 0; r < 4; r++) {
        const int m = m0 + ty * 4 + r;
        float4 v; float* vv = (float*)&v;
        #pragma unroll
        for (int c = 0; c < 4; c++) {
            float x = acc[r][c] + __ldg(&bias[n0 + tx * 4 + c]);
            if (ACT == 1) x = fmaxf(x, 0.0f);
            if (ACT == 2) x = 1.0f / (1.0f + __expf(-x));
            vv[c] = x;
        }
        *(float4*)&C[(size_t)m * OD + n0 + tx * 4] = v;
        if (WRITE_H) {
            __half2 p0 = __float22half2_rn(make_float2(v.x, v.y));
            __half2 p1 = __float22half2_rn(make_float2(v.z, v.w));
            *(uint2*)&Ch[(size_t)m * OD + n0 + tx * 4] =
                make_uint2(*(uint32_t*)&p0, *(uint32_t*)&p1);
        }
    }
}

template <int ACT>
__global__ void __launch_bounds__(128)
gemm_small_kernel(const float* __restrict__ A, const float* __restrict__ W,
                  const float* __restrict__ bias, float* __restrict__ C)
{
    gemm_small_body<ACT, false>(A, W, bias, C, nullptr, blockIdx.y * 64, blockIdx.x * 32);
}

// ---- 128-thread Wo-transpose body: region 32(o) x 64(d) per block ----
__device__ __forceinline__ void transpose_wo_body(
    const float* __restrict__ Wo, __half* __restrict__ T, int bo, int bd)
{
    __shared__ float tile[32][33];
    const int x = threadIdx.x & 31;
    const int y = threadIdx.x >> 5;
    #pragma unroll
    for (int sub = 0; sub < 2; sub++) {
        const int bds = bd + sub * 32;
        #pragma unroll
        for (int r = 0; r < 8; r++)
            tile[y + 4 * r][x] = Wo[(size_t)(bds + y + 4 * r) * OD + bo + x];
        __syncthreads();
        #pragma unroll
        for (int r = 0; r < 8; r++) {
            const int o = bo + y + 4 * r;
            const int d = bds + x;
            T[(size_t)o * DD + d] = __float2half_rn(tile[x][y + 4 * r]);
        }
        __syncthreads();
    }
}

// Fused first stage: z=0 -> h, z=1 -> outx(+outxh), z=2 -> WoT
__global__ void __launch_bounds__(128)
pre_fused_kernel(const float* __restrict__ text, const float* __restrict__ image,
                 const float* __restrict__ Wa1, const float* __restrict__ ba1,
                 const float* __restrict__ Wx,  const float* __restrict__ bx,
                 const float* __restrict__ Wo,
                 float* __restrict__ h, float* __restrict__ outx,
                 __half* __restrict__ outxh, __half* __restrict__ wot)
{
    if (blockIdx.z == 0)
        gemm_small_body<1, false>(text, Wa1, ba1, h, nullptr, blockIdx.y * 64, blockIdx.x * 32);
    else if (blockIdx.z == 1)
        gemm_small_body<0, true>(image, Wx, bx, outx, outxh, blockIdx.y * 64, blockIdx.x * 32);
    else
        transpose_wo_body(Wo, wot, blockIdx.x * 32, blockIdx.y * 64);
}

// ============================================================
// Preamble: row softmax * text
// ============================================================
__global__ void __launch_bounds__(512)
softmax_mul_kernel(const float* __restrict__ logits, const float* __restrict__ text,
                   float* __restrict__ out)
{
    __shared__ float sdata[512];
    const int row = blockIdx.x, t = threadIdx.x;
    const float v = logits[(size_t)row * DD + t];
    sdata[t] = v; __syncthreads();
    for (int s = 256; s > 0; s >>= 1) { if (t < s) sdata[t] = fmaxf(sdata[t], sdata[t + s]); __syncthreads(); }
    const float mx = sdata[0]; __syncthreads();
    const float e = __expf(v - mx);
    sdata[t] = e; __syncthreads();
    for (int s = 256; s > 0; s >>= 1) { if (t < s) sdata[t] += sdata[t + s]; __syncthreads(); }
    out[(size_t)row * DD + t] = e * (1.0f / sdata[0]) * text[(size_t)row * DD + t];
}

__global__ void mul_kernel(const float* __restrict__ a, const float* __restrict__ b,
                           float* __restrict__ c, int n)
{
    int idx = blockIdx.x * blockDim.x + threadIdx.x;
    if (idx < n) c[idx] = a[idx] * b[idx];
}

// ============================================================
// Big einsum, fp16 HMMA, 2 i/CTA with register-pipelined
// fragment loads (R14/R15 best). UNCHANGED — ~97% of the
// measured fp16 HMMA ceiling.
// ============================================================
__global__ void __launch_bounds__(256, 1)
big_einsum_hmma_kernel(const __half* __restrict__ outxh, const float* __restrict__ gate,
                       const float* __restrict__ bo, float* __restrict__ out)
{
    extern __shared__ char dynsmem[];
    float* gs = (float*)dynsmem;
    const uint32_t sbase = smem_u32(dynsmem) + 4096u;

    const int i0 = blockIdx.z * 2;
    const int j0 = blockIdx.y * 128;
    const int o0 = blockIdx.x * 128;
    const int tid  = threadIdx.x;
    const int wid  = tid >> 5;
    const int lane = tid & 31;
    const int warp_m = wid & 3;
    const int warp_n = wid >> 2;

    gs[tid]        = gate[(size_t)i0 * DD + tid];
    gs[tid + 256]  = gate[(size_t)i0 * DD + tid + 256];
    gs[tid + 512]  = gate[(size_t)(i0 + 1) * DD + tid];
    gs[tid + 768]  = gate[(size_t)(i0 + 1) * DD + tid + 256];

    const int arow = tid >> 1;
    const int ach  = (tid & 1) * 32;

    auto cpB = [&](int c, int buf) {
        const int c0 = c * 64;
        const uint32_t bdst = sbase + buf * BUF_BYTES + OFF_B;
        #pragma unroll
        for (int q = 0; q < 4; q++) {
            const int g   = tid + q * 256;
            const int row = g >> 3;
            const int ck  = g & 7;
            const uint32_t dso = (uint32_t)(row * ASTRIDE + ck * 16);
            const __half* src = g_WoT + (size_t)(o0 + row) * DD + c0 + ck * 8;
            CP_ASYNC_16(bdst + dso, src);
        }
        CP_ASYNC_COMMIT();
    };

    uint4 av[4];
    auto loadA = [&](int c) {
        const __half* p = outxh + (size_t)(j0 + arow) * DD + c * 64 + ach;
        #pragma unroll
        for (int q = 0; q < 4; q++) av[q] = __ldg((const uint4*)(p + q * 8));
    };

    auto storeA = [&](int c, int buf) {
        const int d0 = c * 64 + ach;
        #pragma unroll
        for (int iv = 0; iv < 2; iv++) {
            const uint32_t ad = sbase + buf * BUF_BYTES
                              + (iv ? OFF_A1 : OFF_A0) + arow * ASTRIDE + ach * 2;
            const float* gp = gs + iv * 512 + d0;
            #pragma unroll
            for (int h = 0; h < 4; h++) {
                const __half2* xa = (const __half2*)&av[h];
                uint32_t w[4];
                #pragma unroll
                for (int q = 0; q < 4; q++) {
                    float2 xf = __half22float2(xa[q]);
                    const float2 gf = *(const float2*)&gp[h * 8 + q * 2];
                    __half2 r = __float22half2_rn(make_float2(xf.x * gf.x, xf.y * gf.y));
                    w[q] = *(uint32_t*)&r;
                }
                asm volatile("st.shared.v4.b32 [%0], {%1,%2,%3,%4};"
                             :: "r"(ad + h * 16), "r"(w[0]), "r"(w[1]), "r"(w[2]), "r"(w[3]));
            }
        }
    };

    const uint32_t a_lane = (uint32_t)(((lane & 7) + ((lane >> 3) & 1) * 8) * ASTRIDE
                                       + (lane >> 4) * 16);
    const uint32_t b_lane = (uint32_t)(((lane & 7) + (lane >> 4) * 8) * ASTRIDE
                                       + ((lane >> 3) & 1) * 16);
    const uint32_t a_warp = (uint32_t)(warp_m * 32 * ASTRIDE);
    const uint32_t b_warp = (uint32_t)(warp_n * 64 * ASTRIDE);

    float acc0[2][8][4] = {};
    float acc1[2][8][4] = {};

    loadA(0);
    cpB(0, 0);
    __syncthreads();
    storeA(0, 0);
    CP_ASYNC_WAIT0();
    __syncthreads();

    for (int c = 0; c < 8; c++) {
        const int buf = c & 1;
        if (c < 7) { loadA(c + 1); cpB(c + 1, buf ^ 1); }

        const uint32_t bb = sbase + buf * BUF_BYTES;

        uint32_t a0c[2][4], a1c[2][4], bhc[4];
        #pragma unroll
        for (int mt = 0; mt < 2; mt++) {
            ldsm_x4(a0c[mt], bb + OFF_A0 + a_warp + a_lane + mt * 16 * ASTRIDE);
            ldsm_x4(a1c[mt], bb + OFF_A1 + a_warp + a_lane + mt * 16 * ASTRIDE);
        }
        ldsm_x4(bhc, bb + OFF_B + b_warp + b_lane);

        #pragma unroll
        for (int ks = 0; ks < 4; ks++) {
            uint32_t a0n[2][4], a1n[2][4];
            #pragma unroll
            for (int g = 0; g < 4; g++) {
                uint32_t bhn[4];
                if (g < 3) {
                    ldsm_x4(bhn, bb + OFF_B + b_warp + b_lane
                                  + (g + 1) * 16 * ASTRIDE + ks * 32);
                } else if (ks < 3) {
                    #pragma unroll
                    for (int mt = 0; mt < 2; mt++) {
                        ldsm_x4(a0n[mt], bb + OFF_A0 + a_warp + a_lane
                                          + mt * 16 * ASTRIDE + (ks + 1) * 32);
                        ldsm_x4(a1n[mt], bb + OFF_A1 + a_warp + a_lane
                                          + mt * 16 * ASTRIDE + (ks + 1) * 32);
                    }
                    ldsm_x4(bhn, bb + OFF_B + b_warp + b_lane + (ks + 1) * 32);
                }
                #pragma unroll
                for (int mt = 0; mt < 2; mt++) {
                    mma_fp16(acc0[mt][g * 2],     a0c[mt], bhc[0], bhc[1]);
                    mma_fp16(acc0[mt][g * 2 + 1], a0c[mt], bhc[2], bhc[3]);
                    mma_fp16(acc1[mt][g * 2],     a1c[mt], bhc[0], bhc[1]);
                    mma_fp16(acc1[mt][g * 2 + 1], a1c[mt], bhc[2], bhc[3]);
                }
                if (g < 3 || ks < 3) {
                    #pragma unroll
                    for (int q = 0; q < 4; q++) bhc[q] = bhn[q];
                }
            }
            if (ks < 3) {
                #pragma unroll
                for (int mt = 0; mt < 2; mt++)
                    #pragma unroll
                    for (int q = 0; q < 4; q++) {
                        a0c[mt][q] = a0n[mt][q];
                        a1c[mt][q] = a1n[mt][q];
                    }
            }
        }

        if (c < 7) {
            storeA(c + 1, buf ^ 1);
            CP_ASYNC_WAIT0();
            __syncthreads();
        }
    }

    const int colb = o0 + warp_n * 64 + (lane & 3) * 2;
    float2 bv[8];
    #pragma unroll
    for (int nj = 0; nj < 8; nj++)
        bv[nj] = __ldg((const float2*)&bo[colb + nj * 8]);

    const int rowb = j0 + warp_m * 32 + (lane >> 2);
    #pragma unroll
    for (int iv = 0; iv < 2; iv++) {
        #pragma unroll
        for (int mt = 0; mt < 2; mt++) {
            #pragma unroll
            for (int h = 0; h < 2; h++) {
                const size_t rbase = ((size_t)(i0 + iv) * NB + (rowb + mt * 16 + h * 8)) * OD;
                #pragma unroll
                for (int nj = 0; nj < 8; nj++) {
                    const float* a = iv ? acc1[mt][nj] : acc0[mt][nj];
                    float2 v;
                    v.x = a[h * 2]     + bv[nj].x;
                    v.y = a[h * 2 + 1] + bv[nj].y;
                    *(float2*)&out[rbase + colb + nj * 8] = v;
                }
            }
        }
    }
}

// ============================================================
// kernel_launch
// ============================================================
extern "C" void kernel_launch(void* const* d_in, const int* in_sizes, int n_in,
                              void* d_out, int out_size)
{
    const float* image = (const float*)d_in[0];
    const float* text  = (const float*)d_in[1];
    const float* Wx  = (const float*)d_in[3];
    const float* bx  = (const float*)d_in[4];
    const float* Wy  = (const float*)d_in[5];
    const float* by  = (const float*)d_in[6];
    const float* Wo  = (const float*)d_in[7];
    const float* bo  = (const float*)d_in[8];
    const float* Wa1 = (const float*)d_in[9];
    const float* ba1 = (const float*)d_in[10];
    const float* Wa2 = (const float*)d_in[11];
    const float* ba2 = (const float*)d_in[12];
    float* out = (float*)d_out;

    float *h, *logits, *textw, *outx, *gate, *tmp;
    __half *wot, *outxh;
    cudaGetSymbolAddress((void**)&h,      g_h);
    cudaGetSymbolAddress((void**)&logits, g_logits);
    cudaGetSymbolAddress((void**)&textw,  g_textw);
    cudaGetSymbolAddress((void**)&outx,   g_outx);
    cudaGetSymbolAddress((void**)&gate,   g_gate);
    cudaGetSymbolAddress((void**)&tmp,    g_tmp);
    cudaGetSymbolAddress((void**)&wot,    g_WoT);
    cudaGetSymbolAddress((void**)&outxh,  g_outxh);

    cudaFuncSetAttribute(big_einsum_hmma_kernel,
                         cudaFuncAttributeMaxDynamicSharedMemorySize, SMEM_BYTES);

    const dim3 gsm(OD / 32, NB / 64);   // (16, 8) = 128 CTAs

    // Stage 1 fused: h, outx(+outxh), WoT transpose — one launch
    pre_fused_kernel<<<dim3(OD / 32, NB / 64, 3), 128>>>(text, image, Wa1, ba1, Wx, bx,
                                                         Wo, h, outx, outxh, wot);
    // logits = h@Wa2+ba2
    gemm_small_kernel<0><<<gsm, 128>>>(h, Wa2, ba2, logits);
    // textw = softmax(logits) * text
    softmax_mul_kernel<<<NB, 512>>>(logits, text, textw);
    // gate = sigmoid(textw@Wy+by)
    gemm_small_kernel<2><<<gsm, 128>>>(textw, Wy, by, gate);

    if (out_size == NB * NB * OD) {
        dim3 grid(OD / 128, NB / 128, NB / 2);   // (4, 4, 256)
        big_einsum_hmma_kernel<<<grid, 256, SMEM_BYTES>>>(outxh, gate, bo, out);
    } else {
        mul_kernel<<<(NB * DD + 255) / 256, 256>>>(gate, outx, tmp, NB * DD);
        gemm_small_kernel<0><<<gsm, 128>>>(tmp, Wo, bo, out);
    }
}